// round 12
// baseline (speedup 1.0000x reference)
#include <cuda_runtime.h>
#include <cstdint>

// Skeleton forward kinematics: 6d rotations -> world-space joint positions.
// angles: [B, 16, 6] f32   xyz: [1, 16, 3] f32   out: [B, 16, 3] f32
//
// Round-12: v11 (33.1us kernel) with exactly ONE change: staging uses
// cp.async.cg (gmem -> smem direct). Deletes 24 STS.128 per thread (-22% of
// L1tex wavefront pressure), the LDG->STS scoreboard chain, and its register
// buffering. Everything else -- TPB=128 tile, pitch-129 float4 layout, flush
// schedule, 3 barriers, coalesced gather, associativity-optimized step --
// is byte-identical to v11.

namespace {

constexpr int NJ   = 16;
constexpr int TPB  = 128;
constexpr int PIT  = 129;                       // float4 pitch (odd -> conflict-free)
constexpr size_t SMEM_BYTES = 24 * PIT * sizeof(float4) + 48 * sizeof(float);

__device__ __forceinline__ void rot6d(const float* __restrict__ a, float R[9]) {
    float n1 = rsqrtf(a[0] * a[0] + a[1] * a[1] + a[2] * a[2]);
    float b1x = a[0] * n1, b1y = a[1] * n1, b1z = a[2] * n1;
    float d = b1x * a[3] + b1y * a[4] + b1z * a[5];
    float b2x = a[3] - d * b1x, b2y = a[4] - d * b1y, b2z = a[5] - d * b1z;
    float n2 = rsqrtf(b2x * b2x + b2y * b2y + b2z * b2z);
    b2x *= n2; b2y *= n2; b2z *= n2;
    R[0] = b1x; R[1] = b1y; R[2] = b1z;
    R[3] = b2x; R[4] = b2y; R[5] = b2z;
    R[6] = b1y * b2z - b1z * b2y;
    R[7] = b1z * b2x - b1x * b2z;
    R[8] = b1x * b2y - b1y * b2x;
}

__global__ __launch_bounds__(TPB)
void skeleton_fk_v12(const float4* __restrict__ angles4,
                     const float*  __restrict__ xyz,
                     float4* __restrict__ out4)
{
    extern __shared__ float4 sa4[];                           // [24 * PIT]
    float* stv = reinterpret_cast<float*>(sa4 + 24 * PIT);    // [48]: ref0 + edges

    const int t = threadIdx.x;
    const size_t tile = (size_t)blockIdx.x * TPB;

    // ---- Stage: cp.async.cg gmem -> smem (transposed), no register hop ----
    const float4* __restrict__ src = angles4 + tile * 24;
#pragma unroll
    for (int k = 0; k < 24; ++k) {
        int g = t + k * TPB;                 // 0..3071
        int b = g / 24;
        int r = g - b * 24;
        uint32_t saddr = (uint32_t)__cvta_generic_to_shared(sa4 + r * PIT + b);
        asm volatile("cp.async.cg.shared.global [%0], [%1], 16;"
                     :: "r"(saddr), "l"(src + g) : "memory");
    }
    asm volatile("cp.async.commit_group;" ::: "memory");

    // stv[0..2] = ref[0]; stv[3c+k] = ref[c] - ref[parent(c)], c = 1..15.
    {
        constexpr int PARENT[15] = {0, 1, 2, 3, 4, 3, 6, 7, 8, 9, 3, 11, 12, 13, 14};
        if (t < 3) stv[t] = __ldg(xyz + t);
        else if (t < 48) {
            int i = t - 3;
            int e = i / 3, k = i - 3 * e;
            stv[t] = __ldg(xyz + 3 * (e + 1) + k) - __ldg(xyz + 3 * PARENT[e] + k);
        }
    }

    asm volatile("cp.async.wait_group 0;" ::: "memory");
    __syncthreads();

    // ---- Compute (v11: sequential order, flush schedule, algebraic step) ----
    {
        float a2[12];
        float pw[48];
        float Rc[9], Rs[9];

        auto loadPair = [&](int j) {         // joints 2j, 2j+1 -> a2[0..11]
            float4 q0 = sa4[(3 * j + 0) * PIT + t];
            float4 q1 = sa4[(3 * j + 1) * PIT + t];
            float4 q2 = sa4[(3 * j + 2) * PIT + t];
            a2[0] = q0.x; a2[1] = q0.y; a2[2]  = q0.z; a2[3]  = q0.w;
            a2[4] = q1.x; a2[5] = q1.y; a2[6]  = q1.z; a2[7]  = q1.w;
            a2[8] = q2.x; a2[9] = q2.y; a2[10] = q2.z; a2[11] = q2.w;
        };
        auto flushRow = [&](int r) {
            sa4[r * PIT + t] = make_float4(pw[4 * r + 0], pw[4 * r + 1],
                                           pw[4 * r + 2], pw[4 * r + 3]);
        };
        auto step = [&](int p, int c, int ao) {
            float R[9];
            rot6d(&a2[ao], R);
            float Rn[9];
#pragma unroll
            for (int i = 0; i < 3; ++i)
#pragma unroll
                for (int k = 0; k < 3; ++k)
                    Rn[3 * i + k] = Rc[3 * i + 0] * R[0 + k]
                                  + Rc[3 * i + 1] * R[3 + k]
                                  + Rc[3 * i + 2] * R[6 + k];
            float tx = stv[3 * c + 0], ty = stv[3 * c + 1], tz = stv[3 * c + 2];
            pw[3 * c + 0] = Rn[0] * tx + Rn[1] * ty + Rn[2] * tz + pw[3 * p + 0];
            pw[3 * c + 1] = Rn[3] * tx + Rn[4] * ty + Rn[5] * tz + pw[3 * p + 1];
            pw[3 * c + 2] = Rn[6] * tx + Rn[7] * ty + Rn[8] * tz + pw[3 * p + 2];
#pragma unroll
            for (int i = 0; i < 9; ++i) Rc[i] = Rn[i];
        };

        // Root joint 0
        loadPair(0);
        rot6d(&a2[0], Rc);
        {
            float x = stv[0], y = stv[1], z = stv[2];
            pw[0] = Rc[0] * x + Rc[1] * y + Rc[2] * z;
            pw[1] = Rc[3] * x + Rc[4] * y + Rc[5] * z;
            pw[2] = Rc[6] * x + Rc[7] * y + Rc[8] * z;
        }

        // Chain 0-1-2-3 (flush row r only after its angle floats consumed)
        step(0, 1, 6);  flushRow(0);
        loadPair(1);
        step(1, 2, 0);  flushRow(1);
        step(2, 3, 6);  flushRow(2);
#pragma unroll
        for (int i = 0; i < 9; ++i) Rs[i] = Rc[i];

        // Branch A: 3-4-5
        loadPair(2);
        step(3, 4, 0);
        step(4, 5, 6);  flushRow(3);

        // Branch B: 3-6-7-8-9-10
#pragma unroll
        for (int i = 0; i < 9; ++i) Rc[i] = Rs[i];
        loadPair(3);
        step(3, 6, 0);  flushRow(4);
        step(6, 7, 6);  flushRow(5);
        loadPair(4);
        step(7, 8, 0);
        step(8, 9, 6);  flushRow(6);
        loadPair(5);
        step(9, 10, 0); flushRow(7);

        // Branch C: 3-11-12-13-14-15
#pragma unroll
        for (int i = 0; i < 9; ++i) Rc[i] = Rs[i];
        step(3, 11, 6);  flushRow(8);
        loadPair(6);
        step(11, 12, 0);
        step(12, 13, 6); flushRow(9);
        loadPair(7);
        step(13, 14, 0); flushRow(10);
        step(14, 15, 6); flushRow(11);
    }

    __syncthreads();

    // ---- Gather: conflict-free LDS.128 -> coalesced STG.128 ----
    float4* __restrict__ dst = out4 + tile * 12;
#pragma unroll
    for (int k = 0; k < 12; ++k) {
        int g = t + k * TPB;                 // 0..1535
        int b = g / 12;
        int r = g - b * 12;
        dst[g] = sa4[r * PIT + b];
    }
}

// Tail fallback (unused: 262144 % 128 == 0; kept for safety).
__global__ void skeleton_fk_tail(const float* __restrict__ angles,
                                 const float* __restrict__ xyz,
                                 float* __restrict__ out,
                                 int start, int batch)
{
    int b = start + blockIdx.x * blockDim.x + threadIdx.x;
    if (b >= batch) return;
    const float* ab = angles + (size_t)b * (NJ * 6);
    float ref[NJ * 3];
#pragma unroll
    for (int i = 0; i < NJ * 3; ++i) ref[i] = __ldg(xyz + i);

    float Rw[NJ * 9], pw[NJ * 3];
    {
        float a[6];
#pragma unroll
        for (int k = 0; k < 6; ++k) a[k] = ab[k];
        rot6d(a, &Rw[0]);
        float x = ref[0], y = ref[1], z = ref[2];
        pw[0] = Rw[0] * x + Rw[1] * y + Rw[2] * z;
        pw[1] = Rw[3] * x + Rw[4] * y + Rw[5] * z;
        pw[2] = Rw[6] * x + Rw[7] * y + Rw[8] * z;
    }
    constexpr int PARENT[15] = {0, 1, 2, 3, 4, 3, 6, 7, 8, 9, 3, 11, 12, 13, 14};
#pragma unroll
    for (int e = 0; e < 15; ++e) {
        const int p = PARENT[e], c = e + 1;
        float a[6];
#pragma unroll
        for (int k = 0; k < 6; ++k) a[k] = ab[6 * c + k];
        float R[9]; rot6d(a, R);
        float tx = ref[3 * c + 0] - ref[3 * p + 0];
        float ty = ref[3 * c + 1] - ref[3 * p + 1];
        float tz = ref[3 * c + 2] - ref[3 * p + 2];
        const float* pR = &Rw[9 * p];
        float* nR = &Rw[9 * c];
#pragma unroll
        for (int i = 0; i < 3; ++i)
#pragma unroll
            for (int k = 0; k < 3; ++k)
                nR[3 * i + k] = pR[3 * i + 0] * R[k] + pR[3 * i + 1] * R[3 + k]
                              + pR[3 * i + 2] * R[6 + k];
        pw[3 * c + 0] = nR[0] * tx + nR[1] * ty + nR[2] * tz + pw[3 * p + 0];
        pw[3 * c + 1] = nR[3] * tx + nR[4] * ty + nR[5] * tz + pw[3 * p + 1];
        pw[3 * c + 2] = nR[6] * tx + nR[7] * ty + nR[8] * tz + pw[3 * p + 2];
    }
    float* o = out + (size_t)b * (NJ * 3);
#pragma unroll
    for (int i = 0; i < NJ * 3; ++i) o[i] = pw[i];
}

}  // namespace

extern "C" void kernel_launch(void* const* d_in, const int* in_sizes, int n_in,
                              void* d_out, int out_size) {
    const float* angles = (const float*)d_in[0];
    const float* xyz    = (const float*)d_in[1];
    float* out          = (float*)d_out;

    const int batch = in_sizes[0] / (NJ * 6);
    const int full  = batch / TPB;

    cudaFuncSetAttribute(skeleton_fk_v12,
                         cudaFuncAttributeMaxDynamicSharedMemorySize,
                         (int)SMEM_BYTES);

    if (full > 0) {
        skeleton_fk_v12<<<full, TPB, SMEM_BYTES>>>(
            (const float4*)angles, xyz, (float4*)out);
    }
    const int rem = batch - full * TPB;
    if (rem > 0) {
        skeleton_fk_tail<<<(rem + 127) / 128, 128>>>(angles, xyz, out,
                                                     full * TPB, batch);
    }
}

// round 13
// speedup vs baseline: 1.1417x; 1.1417x over previous
#include <cuda_runtime.h>
#include <cstdint>

// Skeleton forward kinematics: 6d rotations -> world-space joint positions.
// angles: [B, 16, 6] f32   xyz: [1, 16, 3] f32   out: [B, 16, 3] f32
//
// Round-13: warp-autonomous strips with BALANCED SMSPs. TPB=128 (4 warps);
// each warp owns a private 32-element strip ([24 rows][pitch 33] float4).
// stage (plain LDG->STS, proven best) -> __syncwarp -> compute (v11
// algebraic step + flush-into-consumed-rows) -> __syncwarp -> coalesced
// gather. No block-wide barriers: each warp's stage latency overlaps other
// warps' compute. 51.5 KB/block -> 4 blocks/SM = 16 warps (same as v3).

namespace {

constexpr int NJ    = 16;
constexpr int TPB   = 128;
constexpr int WPB   = 4;                 // warps per block (SMSP-balanced)
constexpr int WPIT  = 33;                // per-strip float4 pitch (odd)
constexpr int STRIP = 24 * WPIT;         // float4s per strip
constexpr size_t SMEM_BYTES =
    (size_t)WPB * STRIP * sizeof(float4) + (size_t)WPB * 48 * sizeof(float);

__constant__ int c_parent[15] = {0, 1, 2, 3, 4, 3, 6, 7, 8, 9, 3, 11, 12, 13, 14};

__device__ __forceinline__ void rot6d(const float* __restrict__ a, float R[9]) {
    float n1 = rsqrtf(a[0] * a[0] + a[1] * a[1] + a[2] * a[2]);
    float b1x = a[0] * n1, b1y = a[1] * n1, b1z = a[2] * n1;
    float d = b1x * a[3] + b1y * a[4] + b1z * a[5];
    float b2x = a[3] - d * b1x, b2y = a[4] - d * b1y, b2z = a[5] - d * b1z;
    float n2 = rsqrtf(b2x * b2x + b2y * b2y + b2z * b2z);
    b2x *= n2; b2y *= n2; b2z *= n2;
    R[0] = b1x; R[1] = b1y; R[2] = b1z;
    R[3] = b2x; R[4] = b2y; R[5] = b2z;
    R[6] = b1y * b2z - b1z * b2y;
    R[7] = b1z * b2x - b1x * b2z;
    R[8] = b1x * b2y - b1y * b2x;
}

__global__ __launch_bounds__(TPB)
void skeleton_fk_v13(const float4* __restrict__ angles4,
                     const float*  __restrict__ xyz,
                     float4* __restrict__ out4)
{
    extern __shared__ float4 smem[];
    const int l = threadIdx.x & 31;
    const int w = threadIdx.x >> 5;

    float4* __restrict__ strip = smem + w * STRIP;
    float*  __restrict__ stv   =
        reinterpret_cast<float*>(smem + WPB * STRIP) + w * 48;

    const size_t eBase = ((size_t)blockIdx.x * WPB + w) * 32;

    // ---- Stage: coalesced LDG.128 -> conflict-free STS.128 (warp-local) ----
    const float4* __restrict__ src = angles4 + eBase * 24;
#pragma unroll
    for (int k = 0; k < 24; ++k) {
        int g = l + k * 32;                  // 0..767
        int b = g / 24;
        int r = g - b * 24;
        strip[r * WPIT + b] = __ldg(src + g);
    }

    // Per-warp edge vectors: stv[0..2] = ref[0]; stv[3c+k] = ref[c]-ref[par(c)].
#pragma unroll
    for (int i = l; i < 48; i += 32) {
        if (i < 3) {
            stv[i] = __ldg(xyz + i);
        } else {
            int e = (i - 3) / 3, k = (i - 3) % 3;
            stv[i] = __ldg(xyz + 3 * (e + 1) + k) - __ldg(xyz + 3 * c_parent[e] + k);
        }
    }
    __syncwarp();

    // ---- Compute (v11: sequential order, flush schedule, algebraic step) ----
    {
        float a2[12];
        float pw[48];
        float Rc[9], Rs[9];

        auto loadPair = [&](int j) {         // joints 2j, 2j+1 -> a2[0..11]
            float4 q0 = strip[(3 * j + 0) * WPIT + l];
            float4 q1 = strip[(3 * j + 1) * WPIT + l];
            float4 q2 = strip[(3 * j + 2) * WPIT + l];
            a2[0] = q0.x; a2[1] = q0.y; a2[2]  = q0.z; a2[3]  = q0.w;
            a2[4] = q1.x; a2[5] = q1.y; a2[6]  = q1.z; a2[7]  = q1.w;
            a2[8] = q2.x; a2[9] = q2.y; a2[10] = q2.z; a2[11] = q2.w;
        };
        auto flushRow = [&](int r) {
            strip[r * WPIT + l] = make_float4(pw[4 * r + 0], pw[4 * r + 1],
                                              pw[4 * r + 2], pw[4 * r + 3]);
        };
        auto step = [&](int p, int c, int ao) {
            float R[9];
            rot6d(&a2[ao], R);
            float Rn[9];
#pragma unroll
            for (int i = 0; i < 3; ++i)
#pragma unroll
                for (int k = 0; k < 3; ++k)
                    Rn[3 * i + k] = Rc[3 * i + 0] * R[0 + k]
                                  + Rc[3 * i + 1] * R[3 + k]
                                  + Rc[3 * i + 2] * R[6 + k];
            float tx = stv[3 * c + 0], ty = stv[3 * c + 1], tz = stv[3 * c + 2];
            pw[3 * c + 0] = Rn[0] * tx + Rn[1] * ty + Rn[2] * tz + pw[3 * p + 0];
            pw[3 * c + 1] = Rn[3] * tx + Rn[4] * ty + Rn[5] * tz + pw[3 * p + 1];
            pw[3 * c + 2] = Rn[6] * tx + Rn[7] * ty + Rn[8] * tz + pw[3 * p + 2];
#pragma unroll
            for (int i = 0; i < 9; ++i) Rc[i] = Rn[i];
        };

        // Root joint 0
        loadPair(0);
        rot6d(&a2[0], Rc);
        {
            float x = stv[0], y = stv[1], z = stv[2];
            pw[0] = Rc[0] * x + Rc[1] * y + Rc[2] * z;
            pw[1] = Rc[3] * x + Rc[4] * y + Rc[5] * z;
            pw[2] = Rc[6] * x + Rc[7] * y + Rc[8] * z;
        }

        // Chain 0-1-2-3 (flush row r only after its angle floats consumed)
        step(0, 1, 6);  flushRow(0);
        loadPair(1);
        step(1, 2, 0);  flushRow(1);
        step(2, 3, 6);  flushRow(2);
#pragma unroll
        for (int i = 0; i < 9; ++i) Rs[i] = Rc[i];

        // Branch A: 3-4-5
        loadPair(2);
        step(3, 4, 0);
        step(4, 5, 6);  flushRow(3);

        // Branch B: 3-6-7-8-9-10
#pragma unroll
        for (int i = 0; i < 9; ++i) Rc[i] = Rs[i];
        loadPair(3);
        step(3, 6, 0);  flushRow(4);
        step(6, 7, 6);  flushRow(5);
        loadPair(4);
        step(7, 8, 0);
        step(8, 9, 6);  flushRow(6);
        loadPair(5);
        step(9, 10, 0); flushRow(7);

        // Branch C: 3-11-12-13-14-15
#pragma unroll
        for (int i = 0; i < 9; ++i) Rc[i] = Rs[i];
        step(3, 11, 6);  flushRow(8);
        loadPair(6);
        step(11, 12, 0);
        step(12, 13, 6); flushRow(9);
        loadPair(7);
        step(13, 14, 0); flushRow(10);
        step(14, 15, 6); flushRow(11);
    }

    __syncwarp();

    // ---- Gather: conflict-free LDS.128 -> coalesced STG.128 (warp-local) ----
    float4* __restrict__ dst = out4 + eBase * 12;
#pragma unroll
    for (int k = 0; k < 12; ++k) {
        int g = l + k * 32;                  // 0..383
        int b = g / 12;
        int r = g - b * 12;
        dst[g] = strip[r * WPIT + b];
    }
}

// Tail fallback (unused: 262144 % 128 == 0; kept for safety).
__global__ void skeleton_fk_tail(const float* __restrict__ angles,
                                 const float* __restrict__ xyz,
                                 float* __restrict__ out,
                                 int start, int batch)
{
    int b = start + blockIdx.x * blockDim.x + threadIdx.x;
    if (b >= batch) return;
    const float* ab = angles + (size_t)b * (NJ * 6);
    float ref[NJ * 3];
#pragma unroll
    for (int i = 0; i < NJ * 3; ++i) ref[i] = __ldg(xyz + i);

    float Rw[NJ * 9], pw[NJ * 3];
    {
        float a[6];
#pragma unroll
        for (int k = 0; k < 6; ++k) a[k] = ab[k];
        rot6d(a, &Rw[0]);
        float x = ref[0], y = ref[1], z = ref[2];
        pw[0] = Rw[0] * x + Rw[1] * y + Rw[2] * z;
        pw[1] = Rw[3] * x + Rw[4] * y + Rw[5] * z;
        pw[2] = Rw[6] * x + Rw[7] * y + Rw[8] * z;
    }
#pragma unroll
    for (int e = 0; e < 15; ++e) {
        const int p = c_parent[e], c = e + 1;
        float a[6];
#pragma unroll
        for (int k = 0; k < 6; ++k) a[k] = ab[6 * c + k];
        float R[9]; rot6d(a, R);
        float tx = ref[3 * c + 0] - ref[3 * p + 0];
        float ty = ref[3 * c + 1] - ref[3 * p + 1];
        float tz = ref[3 * c + 2] - ref[3 * p + 2];
        const float* pR = &Rw[9 * p];
        float* nR = &Rw[9 * c];
#pragma unroll
        for (int i = 0; i < 3; ++i)
#pragma unroll
            for (int k = 0; k < 3; ++k)
                nR[3 * i + k] = pR[3 * i + 0] * R[k] + pR[3 * i + 1] * R[3 + k]
                              + pR[3 * i + 2] * R[6 + k];
        pw[3 * c + 0] = nR[0] * tx + nR[1] * ty + nR[2] * tz + pw[3 * p + 0];
        pw[3 * c + 1] = nR[3] * tx + nR[4] * ty + nR[5] * tz + pw[3 * p + 1];
        pw[3 * c + 2] = nR[6] * tx + nR[7] * ty + nR[8] * tz + pw[3 * p + 2];
    }
    float* o = out + (size_t)b * (NJ * 3);
#pragma unroll
    for (int i = 0; i < NJ * 3; ++i) o[i] = pw[i];
}

}  // namespace

extern "C" void kernel_launch(void* const* d_in, const int* in_sizes, int n_in,
                              void* d_out, int out_size) {
    const float* angles = (const float*)d_in[0];
    const float* xyz    = (const float*)d_in[1];
    float* out          = (float*)d_out;

    const int batch = in_sizes[0] / (NJ * 6);
    const int full  = batch / TPB;

    cudaFuncSetAttribute(skeleton_fk_v13,
                         cudaFuncAttributeMaxDynamicSharedMemorySize,
                         (int)SMEM_BYTES);

    if (full > 0) {
        skeleton_fk_v13<<<full, TPB, SMEM_BYTES>>>(
            (const float4*)angles, xyz, (float4*)out);
    }
    const int rem = batch - full * TPB;
    if (rem > 0) {
        skeleton_fk_tail<<<(rem + 127) / 128, 128>>>(angles, xyz, out,
                                                     full * TPB, batch);
    }
}

// round 14
// speedup vs baseline: 1.1657x; 1.0210x over previous
#include <cuda_runtime.h>
#include <cstdint>

// Skeleton forward kinematics: 6d rotations -> world-space joint positions.
// angles: [B, 16, 6] f32   xyz: [1, 16, 3] f32   out: [B, 16, 3] f32
//
// Round-14: v11 (33.1us kernel) with ONE change: the compute phase
// software-pipelines the per-pair angle loads one pair ahead using two a2
// buffers. Each pair's 3 LDS.128 issue ~1 FK-step before first use and
// BEFORE intervening flushRow STS in source order, so smem alias ordering
// cannot serialize LDS behind STS and the 29-cyc LDS latency is hidden.

namespace {

constexpr int NJ   = 16;
constexpr int TPB  = 128;
constexpr int PIT  = 129;                       // float4 pitch (odd -> conflict-free)
constexpr size_t SMEM_BYTES = 24 * PIT * sizeof(float4) + 48 * sizeof(float);

__device__ __forceinline__ void rot6d(const float* __restrict__ a, float R[9]) {
    float n1 = rsqrtf(a[0] * a[0] + a[1] * a[1] + a[2] * a[2]);
    float b1x = a[0] * n1, b1y = a[1] * n1, b1z = a[2] * n1;
    float d = b1x * a[3] + b1y * a[4] + b1z * a[5];
    float b2x = a[3] - d * b1x, b2y = a[4] - d * b1y, b2z = a[5] - d * b1z;
    float n2 = rsqrtf(b2x * b2x + b2y * b2y + b2z * b2z);
    b2x *= n2; b2y *= n2; b2z *= n2;
    R[0] = b1x; R[1] = b1y; R[2] = b1z;
    R[3] = b2x; R[4] = b2y; R[5] = b2z;
    R[6] = b1y * b2z - b1z * b2y;
    R[7] = b1z * b2x - b1x * b2z;
    R[8] = b1x * b2y - b1y * b2x;
}

__global__ __launch_bounds__(TPB)
void skeleton_fk_v14(const float4* __restrict__ angles4,
                     const float*  __restrict__ xyz,
                     float4* __restrict__ out4)
{
    extern __shared__ float4 sa4[];                           // [24 * PIT]
    float* stv = reinterpret_cast<float*>(sa4 + 24 * PIT);    // [48]: ref0 + edges

    const int t = threadIdx.x;
    const size_t tile = (size_t)blockIdx.x * TPB;

    // ---- Stage: coalesced LDG.128 -> conflict-free STS.128 ----
    const float4* __restrict__ src = angles4 + tile * 24;
#pragma unroll
    for (int k = 0; k < 24; ++k) {
        int g = t + k * TPB;                 // 0..3071
        int b = g / 24;
        int r = g - b * 24;
        sa4[r * PIT + b] = __ldg(src + g);
    }
    // stv[0..2] = ref[0]; stv[3c+k] = ref[c] - ref[parent(c)], c = 1..15.
    {
        constexpr int PARENT[15] = {0, 1, 2, 3, 4, 3, 6, 7, 8, 9, 3, 11, 12, 13, 14};
        if (t < 3) stv[t] = __ldg(xyz + t);
        else if (t < 48) {
            int i = t - 3;
            int e = i / 3, k = i - 3 * e;
            stv[t] = __ldg(xyz + 3 * (e + 1) + k) - __ldg(xyz + 3 * PARENT[e] + k);
        }
    }
    __syncthreads();

    // ---- Compute: pair loads pipelined one ahead (double-buffered a2) ----
    {
        float aA[12], aB[12];
        float pw[48];
        float Rc[9], Rs[9];

        auto loadInto = [&](float* dstBuf, int j) {   // joints 2j, 2j+1
            float4 q0 = sa4[(3 * j + 0) * PIT + t];
            float4 q1 = sa4[(3 * j + 1) * PIT + t];
            float4 q2 = sa4[(3 * j + 2) * PIT + t];
            dstBuf[0] = q0.x; dstBuf[1] = q0.y; dstBuf[2]  = q0.z; dstBuf[3]  = q0.w;
            dstBuf[4] = q1.x; dstBuf[5] = q1.y; dstBuf[6]  = q1.z; dstBuf[7]  = q1.w;
            dstBuf[8] = q2.x; dstBuf[9] = q2.y; dstBuf[10] = q2.z; dstBuf[11] = q2.w;
        };
        auto flushRow = [&](int r) {
            sa4[r * PIT + t] = make_float4(pw[4 * r + 0], pw[4 * r + 1],
                                           pw[4 * r + 2], pw[4 * r + 3]);
        };
        auto step = [&](int p, int c, const float* a6) {
            float R[9];
            rot6d(a6, R);
            float Rn[9];
#pragma unroll
            for (int i = 0; i < 3; ++i)
#pragma unroll
                for (int k = 0; k < 3; ++k)
                    Rn[3 * i + k] = Rc[3 * i + 0] * R[0 + k]
                                  + Rc[3 * i + 1] * R[3 + k]
                                  + Rc[3 * i + 2] * R[6 + k];
            float tx = stv[3 * c + 0], ty = stv[3 * c + 1], tz = stv[3 * c + 2];
            pw[3 * c + 0] = Rn[0] * tx + Rn[1] * ty + Rn[2] * tz + pw[3 * p + 0];
            pw[3 * c + 1] = Rn[3] * tx + Rn[4] * ty + Rn[5] * tz + pw[3 * p + 1];
            pw[3 * c + 2] = Rn[6] * tx + Rn[7] * ty + Rn[8] * tz + pw[3 * p + 2];
#pragma unroll
            for (int i = 0; i < 9; ++i) Rc[i] = Rn[i];
        };

        // Prologue: pair 0 -> A, pair 1 -> B (both in flight before any use).
        loadInto(aA, 0);
        loadInto(aB, 1);

        // Root joint 0 (pair 0 in A)
        rot6d(&aA[0], Rc);
        {
            float x = stv[0], y = stv[1], z = stv[2];
            pw[0] = Rc[0] * x + Rc[1] * y + Rc[2] * z;
            pw[1] = Rc[3] * x + Rc[4] * y + Rc[5] * z;
            pw[2] = Rc[6] * x + Rc[7] * y + Rc[8] * z;
        }
        step(0, 1, &aA[6]);  flushRow(0);

        loadInto(aA, 2);                     // prefetch pair 2 (A free)
        step(1, 2, &aB[0]);  flushRow(1);
        step(2, 3, &aB[6]);  flushRow(2);
#pragma unroll
        for (int i = 0; i < 9; ++i) Rs[i] = Rc[i];

        loadInto(aB, 3);                     // prefetch pair 3
        // Branch A: 3-4-5 (pair 2 in A)
        step(3, 4, &aA[0]);
        step(4, 5, &aA[6]);  flushRow(3);

        loadInto(aA, 4);                     // prefetch pair 4
        // Branch B: 3-6-7 (pair 3 in B)
#pragma unroll
        for (int i = 0; i < 9; ++i) Rc[i] = Rs[i];
        step(3, 6, &aB[0]);  flushRow(4);
        step(6, 7, &aB[6]);  flushRow(5);

        loadInto(aB, 5);                     // prefetch pair 5
        // 7-8-9 (pair 4 in A)
        step(7, 8, &aA[0]);
        step(8, 9, &aA[6]);  flushRow(6);

        loadInto(aA, 6);                     // prefetch pair 6
        // 9-10 (pair 5 low in B), branch C start 3-11 (pair 5 high in B)
        step(9, 10, &aB[0]); flushRow(7);
#pragma unroll
        for (int i = 0; i < 9; ++i) Rc[i] = Rs[i];
        step(3, 11, &aB[6]); flushRow(8);

        loadInto(aB, 7);                     // prefetch pair 7
        // 11-12-13 (pair 6 in A)
        step(11, 12, &aA[0]);
        step(12, 13, &aA[6]); flushRow(9);

        // 13-14-15 (pair 7 in B)
        step(13, 14, &aB[0]); flushRow(10);
        step(14, 15, &aB[6]); flushRow(11);
    }

    __syncthreads();

    // ---- Gather: conflict-free LDS.128 -> coalesced STG.128 ----
    float4* __restrict__ dst = out4 + tile * 12;
#pragma unroll
    for (int k = 0; k < 12; ++k) {
        int g = t + k * TPB;                 // 0..1535
        int b = g / 12;
        int r = g - b * 12;
        dst[g] = sa4[r * PIT + b];
    }
}

// Tail fallback (unused: 262144 % 128 == 0; kept for safety).
__global__ void skeleton_fk_tail(const float* __restrict__ angles,
                                 const float* __restrict__ xyz,
                                 float* __restrict__ out,
                                 int start, int batch)
{
    int b = start + blockIdx.x * blockDim.x + threadIdx.x;
    if (b >= batch) return;
    const float* ab = angles + (size_t)b * (NJ * 6);
    float ref[NJ * 3];
#pragma unroll
    for (int i = 0; i < NJ * 3; ++i) ref[i] = __ldg(xyz + i);

    float Rw[NJ * 9], pw[NJ * 3];
    {
        float a[6];
#pragma unroll
        for (int k = 0; k < 6; ++k) a[k] = ab[k];
        rot6d(a, &Rw[0]);
        float x = ref[0], y = ref[1], z = ref[2];
        pw[0] = Rw[0] * x + Rw[1] * y + Rw[2] * z;
        pw[1] = Rw[3] * x + Rw[4] * y + Rw[5] * z;
        pw[2] = Rw[6] * x + Rw[7] * y + Rw[8] * z;
    }
    constexpr int PARENT[15] = {0, 1, 2, 3, 4, 3, 6, 7, 8, 9, 3, 11, 12, 13, 14};
#pragma unroll
    for (int e = 0; e < 15; ++e) {
        const int p = PARENT[e], c = e + 1;
        float a[6];
#pragma unroll
        for (int k = 0; k < 6; ++k) a[k] = ab[6 * c + k];
        float R[9]; rot6d(a, R);
        float tx = ref[3 * c + 0] - ref[3 * p + 0];
        float ty = ref[3 * c + 1] - ref[3 * p + 1];
        float tz = ref[3 * c + 2] - ref[3 * p + 2];
        const float* pR = &Rw[9 * p];
        float* nR = &Rw[9 * c];
#pragma unroll
        for (int i = 0; i < 3; ++i)
#pragma unroll
            for (int k = 0; k < 3; ++k)
                nR[3 * i + k] = pR[3 * i + 0] * R[k] + pR[3 * i + 1] * R[3 + k]
                              + pR[3 * i + 2] * R[6 + k];
        pw[3 * c + 0] = nR[0] * tx + nR[1] * ty + nR[2] * tz + pw[3 * p + 0];
        pw[3 * c + 1] = nR[3] * tx + nR[4] * ty + nR[5] * tz + pw[3 * p + 1];
        pw[3 * c + 2] = nR[6] * tx + nR[7] * ty + nR[8] * tz + pw[3 * p + 2];
    }
    float* o = out + (size_t)b * (NJ * 3);
#pragma unroll
    for (int i = 0; i < NJ * 3; ++i) o[i] = pw[i];
}

}  // namespace

extern "C" void kernel_launch(void* const* d_in, const int* in_sizes, int n_in,
                              void* d_out, int out_size) {
    const float* angles = (const float*)d_in[0];
    const float* xyz    = (const float*)d_in[1];
    float* out          = (float*)d_out;

    const int batch = in_sizes[0] / (NJ * 6);
    const int full  = batch / TPB;

    cudaFuncSetAttribute(skeleton_fk_v14,
                         cudaFuncAttributeMaxDynamicSharedMemorySize,
                         (int)SMEM_BYTES);

    if (full > 0) {
        skeleton_fk_v14<<<full, TPB, SMEM_BYTES>>>(
            (const float4*)angles, xyz, (float4*)out);
    }
    const int rem = batch - full * TPB;
    if (rem > 0) {
        skeleton_fk_tail<<<(rem + 127) / 128, 128>>>(angles, xyz, out,
                                                     full * TPB, batch);
    }
}